// round 12
// baseline (speedup 1.0000x reference)
#include <cuda_runtime.h>

#define HDIM 64
#define NUM_GRAD_STEPS 4
#define INNER_LR 0.01f

typedef unsigned long long u64;

// ---- packed fp32x2 helpers (ptxas won't auto-fuse; PTX fma.rn.f32x2) ----
__device__ __forceinline__ u64 pack2(float lo, float hi) {
    u64 r; asm("mov.b64 %0, {%1,%2};" : "=l"(r) : "f"(lo), "f"(hi)); return r;
}
__device__ __forceinline__ float2 unpack2(u64 v) {
    float2 f; asm("mov.b64 {%0,%1}, %2;" : "=f"(f.x), "=f"(f.y) : "l"(v)); return f;
}
__device__ __forceinline__ u64 fma2(u64 a, u64 b, u64 c) {
    u64 d; asm("fma.rn.f32x2 %0, %1, %2, %3;" : "=l"(d) : "l"(a), "l"(b), "l"(c)); return d;
}
// warp f32 sum: butterfly shfl (redux.sync.add.f32 unsupported on sm_103)
__device__ __forceinline__ float warp_sum(float v) {
    #pragma unroll
    for (int off = 16; off; off >>= 1)
        v += __shfl_xor_sync(0xffffffffu, v, off);
    return v;
}

// fast tanh via MUFU: r = 1/(exp(2x)+1); tanh = 1-2r; 1-tanh^2 = 4r(1-r).
__device__ __forceinline__ float tanh_r(float x) {   // returns r
    const float LOG2E2 = 2.885390081777927f;          // 2*log2(e)
    float e; asm("ex2.approx.f32 %0, %1;" : "=f"(e) : "f"(x * LOG2E2));
    float r; asm("rcp.approx.f32 %0, %1;" : "=f"(r) : "f"(e + 1.0f));
    return r;
}

// One block (64 threads) per batch element. Thread i owns hidden unit i.
// W2 lives ONLY in registers (row i + column i as f32x2 pairs).
// 7 blocks/SM (reg budget 146) -> 1036 concurrent blocks -> 2 waves for
// grid=2048 instead of 3 (the tail wave at 6 blocks/SM was only 31% full).
__global__ __launch_bounds__(64, 7) void ttt_kernel(
    const float* __restrict__ ts, const float* __restrict__ xs,
    const int*   __restrict__ mask,
    const float* __restrict__ W1g, const float* __restrict__ b1g,
    const float* __restrict__ W2g, const float* __restrict__ b2g,
    const float* __restrict__ W3g, const float* __restrict__ b3g,
    float* __restrict__ out, int T)
{
    __shared__ __align__(16) float h1buf[2][HDIM];
    __shared__ __align__(16) float us[HDIM];
    __shared__ float red[2];

    const int b    = blockIdx.x;
    const int i    = threadIdx.x;       // 0..63
    const int lane = i & 31;
    const int warp = i >> 5;

    // ---- load theta0 ----
    u64 w2row[32];   // (W2[i][2m], W2[i][2m+1])
    u64 w2col[32];   // (W2[2m][i], W2[2m+1][i])
    #pragma unroll
    for (int k = 0; k < 16; k++) {
        float4 v = *(const float4*)(W2g + i * HDIM + 4 * k);
        w2row[2 * k]     = pack2(v.x, v.y);
        w2row[2 * k + 1] = pack2(v.z, v.w);
    }
    #pragma unroll
    for (int m = 0; m < 32; m++) {
        float lo = W2g[(2 * m) * HDIM + i];
        float hi = W2g[(2 * m + 1) * HDIM + i];
        w2col[m] = pack2(lo, hi);
    }
    float w1a = W1g[2 * i];
    float w1b = W1g[2 * i + 1];
    float b1i = b1g[i];
    float b2i = b2g[i];
    float w3i = W3g[i];
    float b3  = b3g[0];

    const float* xrow = xs + (size_t)b * T;
    const int*   mrow = mask + (size_t)b * (T - 1);

    const float x0 = xrow[0];
    float x_prev = x0;
    if (i == 0) out[(size_t)b * T] = x0;
    __syncthreads();

    for (int s = 1; s < T; s++) {
        // per-step scalars: L1-resident sequential lines, no prefetch regs
        const float t_c    = ts[s];
        const float x_true = xrow[s];
        const int   mcur   = mrow[s - 1];

        float x_t = 0.f;   // fixed at g0

        #pragma unroll
        for (int g = 0; g < NUM_GRAD_STEPS; g++) {
            float* h1b = h1buf[g & 1];
            // ---- forward at (t_c, x_prev) ----
            const float z1 = fmaf(w1a, t_c, fmaf(w1b, x_prev, b1i));
            const float r1 = tanh_r(z1);
            const float h1 = fmaf(-2.0f, r1, 1.0f);
            h1b[i] = h1;
            __syncthreads();                                  // bar 1

            // matvec: LDS.64 keeps load->fma2 links tight
            const u64* hp = (const u64*)h1b;
            u64 a0 = 0ull, a1 = 0ull, a2 = 0ull, a3 = 0ull;
            #pragma unroll
            for (int k = 0; k < 8; k++) {
                a0 = fma2(w2row[4 * k],     hp[4 * k],     a0);
                a1 = fma2(w2row[4 * k + 1], hp[4 * k + 1], a1);
                a2 = fma2(w2row[4 * k + 2], hp[4 * k + 2], a2);
                a3 = fma2(w2row[4 * k + 3], hp[4 * k + 3], a3);
            }
            float2 s0 = unpack2(a0), s1 = unpack2(a1), s2 = unpack2(a2), s3 = unpack2(a3);
            const float z2 = b2i + (((s0.x + s0.y) + (s1.x + s1.y)) +
                                    ((s2.x + s2.y) + (s3.x + s3.y)));
            const float r2 = tanh_r(z2);
            const float h2 = fmaf(-2.0f, r2, 1.0f);
            const float sech2 = 4.0f * r2 * (1.0f - r2);      // 1 - h2^2

            // warp-partial of pred and the u-broadcast share ONE barrier
            const float u  = w3i * sech2;
            us[i] = u;                      // store first: overlaps shfl chain
            const float pw = warp_sum(w3i * h2);
            if (lane == 0) red[warp] = pw;
            __syncthreads();                                  // bar 2

            const float pred = (red[0] + red[1]) + b3;
            if (g == 0) {   // constant-folded under full unroll
                // pred == x_hat_{s-1} (fusion). Emit it and do TF selection.
                const float xh = (s == 1) ? x0 : pred;
                if (s >= 2 && i == 0) out[(size_t)b * T + s - 1] = pred;
                x_t = (mcur != 0) ? x_true : xh;
            }
            const float dpred = 2.0f * (pred - x_t);
            const float dz2   = dpred * u;                    // own dz2 (old W3)

            w3i = fmaf(-INNER_LR * dpred, h2, w3i);
            b3  = fmaf(-INNER_LR, dpred, b3);
            b2i = fmaf(-INNER_LR, dz2, b2i);

            // row update: W2[i][k] -= lr*dz2_i*h1[k]
            const float amr = -INNER_LR * dz2;
            const u64 amrow = pack2(amr, amr);
            #pragma unroll
            for (int k = 0; k < 8; k++) {
                w2row[4 * k]     = fma2(amrow, hp[4 * k],     w2row[4 * k]);
                w2row[4 * k + 1] = fma2(amrow, hp[4 * k + 1], w2row[4 * k + 1]);
                w2row[4 * k + 2] = fma2(amrow, hp[4 * k + 2], w2row[4 * k + 2]);
                w2row[4 * k + 3] = fma2(amrow, hp[4 * k + 3], w2row[4 * k + 3]);
            }

            // fused column pass: dh1 = dpred * sum_j W2old[j][i]*u[j];
            // W2[j][i] -= lr*(dpred*u[j])*h1_i
            const float amc = -INNER_LR * dpred * h1;
            const u64 amcol = pack2(amc, amc);
            const u64* up = (const u64*)us;
            u64 d0 = 0ull, d1 = 0ull, d2 = 0ull, d3 = 0ull;
            #pragma unroll
            for (int j = 0; j < 8; j++) {
                u64 p0 = up[4 * j],     p1 = up[4 * j + 1];
                u64 p2 = up[4 * j + 2], p3 = up[4 * j + 3];
                d0 = fma2(w2col[4 * j],     p0, d0);
                d1 = fma2(w2col[4 * j + 1], p1, d1);
                d2 = fma2(w2col[4 * j + 2], p2, d2);
                d3 = fma2(w2col[4 * j + 3], p3, d3);
                w2col[4 * j]     = fma2(amcol, p0, w2col[4 * j]);
                w2col[4 * j + 1] = fma2(amcol, p1, w2col[4 * j + 1]);
                w2col[4 * j + 2] = fma2(amcol, p2, w2col[4 * j + 2]);
                w2col[4 * j + 3] = fma2(amcol, p3, w2col[4 * j + 3]);
            }
            float2 e0 = unpack2(d0), e1 = unpack2(d1), e2 = unpack2(d2), e3 = unpack2(d3);
            const float dh1 = dpred * (((e0.x + e0.y) + (e1.x + e1.y)) +
                                       ((e2.x + e2.y) + (e3.x + e3.y)));
            const float sech1 = 4.0f * r1 * (1.0f - r1);      // 1 - h1^2
            const float dz1 = dh1 * sech1;
            w1a = fmaf(-INNER_LR * dz1, t_c,    w1a);
            w1b = fmaf(-INNER_LR * dz1, x_prev, w1b);
            b1i = fmaf(-INNER_LR, dz1, b1i);
        }

        x_prev = x_true;
    }

    // ---- last output: explicit final forward with final theta ----
    {
        const float tl = ts[T - 1], tp = ts[T - 2];
        const float tin = tl + (tl - tp);
        const float zf = fmaf(w1a, tin, fmaf(w1b, x_prev, b1i)); // x_prev = xs[T-1]
        const float hf = fmaf(-2.0f, tanh_r(zf), 1.0f);
        h1buf[0][i] = hf;
        __syncthreads();

        const u64* hp = (const u64*)h1buf[0];
        u64 a0 = 0ull, a1 = 0ull, a2 = 0ull, a3 = 0ull;
        #pragma unroll
        for (int k = 0; k < 8; k++) {
            a0 = fma2(w2row[4 * k],     hp[4 * k],     a0);
            a1 = fma2(w2row[4 * k + 1], hp[4 * k + 1], a1);
            a2 = fma2(w2row[4 * k + 2], hp[4 * k + 2], a2);
            a3 = fma2(w2row[4 * k + 3], hp[4 * k + 3], a3);
        }
        float2 s0 = unpack2(a0), s1 = unpack2(a1), s2 = unpack2(a2), s3 = unpack2(a3);
        const float z2 = b2i + (((s0.x + s0.y) + (s1.x + s1.y)) +
                                ((s2.x + s2.y) + (s3.x + s3.y)));
        const float h2 = fmaf(-2.0f, tanh_r(z2), 1.0f);
        const float pw = warp_sum(w3i * h2);
        if (lane == 0) red[warp] = pw;
        __syncthreads();
        if (i == 0) out[(size_t)b * T + T - 1] = (red[0] + red[1]) + b3;
    }
}

extern "C" void kernel_launch(void* const* d_in, const int* in_sizes, int n_in,
                              void* d_out, int out_size) {
    const float* ts   = (const float*)d_in[0];
    const float* xs   = (const float*)d_in[1];
    const int*   mask = (const int*)  d_in[2];
    const float* W1   = (const float*)d_in[3];
    const float* b1   = (const float*)d_in[4];
    const float* W2   = (const float*)d_in[5];
    const float* b2   = (const float*)d_in[6];
    const float* W3   = (const float*)d_in[7];
    const float* b3   = (const float*)d_in[8];

    const int T = in_sizes[0];
    const int B = in_sizes[1] / T;

    ttt_kernel<<<B, HDIM>>>(ts, xs, mask, W1, b1, W2, b2, W3, b3,
                            (float*)d_out, T);
}

// round 13
// speedup vs baseline: 1.2447x; 1.2447x over previous
#include <cuda_runtime.h>

#define HDIM 64
#define NUM_GRAD_STEPS 4
#define INNER_LR 0.01f

typedef unsigned long long u64;

// ---- packed fp32x2 helpers (ptxas won't auto-fuse; PTX f32x2 ops) ----
__device__ __forceinline__ u64 pack2(float lo, float hi) {
    u64 r; asm("mov.b64 %0, {%1,%2};" : "=l"(r) : "f"(lo), "f"(hi)); return r;
}
__device__ __forceinline__ float2 unpack2(u64 v) {
    float2 f; asm("mov.b64 {%0,%1}, %2;" : "=f"(f.x), "=f"(f.y) : "l"(v)); return f;
}
__device__ __forceinline__ u64 fma2(u64 a, u64 b, u64 c) {
    u64 d; asm("fma.rn.f32x2 %0, %1, %2, %3;" : "=l"(d) : "l"(a), "l"(b), "l"(c)); return d;
}
__device__ __forceinline__ u64 add2(u64 a, u64 b) {
    u64 d; asm("add.rn.f32x2 %0, %1, %2;" : "=l"(d) : "l"(a), "l"(b)); return d;
}

// fast tanh via MUFU: r = 1/(exp(2x)+1); tanh = 1-2r; 1-tanh^2 = 4r(1-r).
__device__ __forceinline__ float tanh_r(float x) {   // returns r
    const float LOG2E2 = 2.885390081777927f;          // 2*log2(e)
    float e; asm("ex2.approx.f32 %0, %1;" : "=f"(e) : "f"(x * LOG2E2));
    float r; asm("rcp.approx.f32 %0, %1;" : "=f"(r) : "f"(e + 1.0f));
    return r;
}

// Redundant full sum of 64 smem floats (identical in every thread; replaces
// the 130-cyc pre-barrier shfl chain with a ~70-cyc post-barrier one).
__device__ __forceinline__ float sum64(const float* p) {
    const float4* p4 = (const float4*)p;
    u64 q0 = 0ull, q1 = 0ull, q2 = 0ull, q3 = 0ull;
    #pragma unroll
    for (int k = 0; k < 8; k++) {
        float4 A = p4[2 * k], B = p4[2 * k + 1];
        q0 = add2(q0, pack2(A.x, A.y));
        q1 = add2(q1, pack2(A.z, A.w));
        q2 = add2(q2, pack2(B.x, B.y));
        q3 = add2(q3, pack2(B.z, B.w));
    }
    u64 q = add2(add2(q0, q1), add2(q2, q3));
    float2 f = unpack2(q);
    return f.x + f.y;
}

// One block (64 threads) per batch element. Thread i owns hidden unit i.
// W2 lives ONLY in registers (row i + column i as f32x2 pairs).
__global__ __launch_bounds__(64, 6) void ttt_kernel(
    const float* __restrict__ ts, const float* __restrict__ xs,
    const int*   __restrict__ mask,
    const float* __restrict__ W1g, const float* __restrict__ b1g,
    const float* __restrict__ W2g, const float* __restrict__ b2g,
    const float* __restrict__ W3g, const float* __restrict__ b3g,
    float* __restrict__ out, int T)
{
    __shared__ __align__(16) float h1buf[2][HDIM];
    __shared__ __align__(16) float us[HDIM];
    __shared__ __align__(16) float pps[HDIM];

    const int b = blockIdx.x;
    const int i = threadIdx.x;          // 0..63

    // ---- load theta0 ----
    u64 w2row[32];   // (W2[i][2m], W2[i][2m+1])
    u64 w2col[32];   // (W2[2m][i], W2[2m+1][i])
    #pragma unroll
    for (int k = 0; k < 16; k++) {
        float4 v = *(const float4*)(W2g + i * HDIM + 4 * k);
        w2row[2 * k]     = pack2(v.x, v.y);
        w2row[2 * k + 1] = pack2(v.z, v.w);
    }
    #pragma unroll
    for (int m = 0; m < 32; m++) {
        float lo = W2g[(2 * m) * HDIM + i];
        float hi = W2g[(2 * m + 1) * HDIM + i];
        w2col[m] = pack2(lo, hi);
    }
    float w1a = W1g[2 * i];
    float w1b = W1g[2 * i + 1];
    float b1i = b1g[i];
    float b2i = b2g[i];
    float w3i = W3g[i];
    float b3  = b3g[0];

    const float* xrow = xs + (size_t)b * T;
    const int*   mrow = mask + (size_t)b * (T - 1);

    const float x0 = xrow[0];
    float x_prev = x0;
    if (i == 0) out[(size_t)b * T] = x0;
    __syncthreads();

    for (int s = 1; s < T; s++) {
        const float t_c    = ts[s];
        const float x_true = xrow[s];
        const int   mcur   = mrow[s - 1];

        float x_t = 0.f;   // fixed at g0

        // z1 recurrence: z1^{g+1} = z1^g - lr*dz1^g*(t^2+x^2+1)  (exact)
        float z1   = fmaf(w1a, t_c, fmaf(w1b, x_prev, b1i));
        const float nrm = fmaf(t_c, t_c, fmaf(x_prev, x_prev, 1.0f));
        float sdz1 = 0.f;   // sum of dz1 over grad steps (W1 materialized once)

        #pragma unroll
        for (int g = 0; g < NUM_GRAD_STEPS; g++) {
            float* h1b = h1buf[g & 1];
            // ---- forward at (t_c, x_prev) ----
            const float r1 = tanh_r(z1);
            const float h1 = fmaf(-2.0f, r1, 1.0f);
            h1b[i] = h1;
            __syncthreads();                                  // bar 1

            // matvec: LDS.64 keeps load->fma2 links tight
            const u64* hp = (const u64*)h1b;
            u64 a0 = 0ull, a1 = 0ull, a2 = 0ull, a3 = 0ull;
            #pragma unroll
            for (int k = 0; k < 8; k++) {
                a0 = fma2(w2row[4 * k],     hp[4 * k],     a0);
                a1 = fma2(w2row[4 * k + 1], hp[4 * k + 1], a1);
                a2 = fma2(w2row[4 * k + 2], hp[4 * k + 2], a2);
                a3 = fma2(w2row[4 * k + 3], hp[4 * k + 3], a3);
            }
            float2 s0 = unpack2(a0), s1 = unpack2(a1), s2 = unpack2(a2), s3 = unpack2(a3);
            const float z2 = b2i + (((s0.x + s0.y) + (s1.x + s1.y)) +
                                    ((s2.x + s2.y) + (s3.x + s3.y)));
            const float r2 = tanh_r(z2);
            const float h2 = fmaf(-2.0f, r2, 1.0f);
            const float sech2 = 4.0f * r2 * (1.0f - r2);      // 1 - h2^2

            // broadcast u and the pred partial under ONE barrier (no shfl chain)
            us[i]  = w3i * sech2;
            pps[i] = w3i * h2;
            __syncthreads();                                  // bar 2

            const float u    = us[i];
            const float pred = sum64(pps) + b3;               // redundant, identical
            if (g == 0) {   // constant-folded under full unroll
                // pred == x_hat_{s-1} (fusion). Emit it and do TF selection.
                const float xh = (s == 1) ? x0 : pred;
                if (s >= 2 && i == 0) out[(size_t)b * T + s - 1] = pred;
                x_t = (mcur != 0) ? x_true : xh;
            }
            const float dpred = 2.0f * (pred - x_t);
            const float dz2   = dpred * u;                    // own dz2 (old W3)

            w3i = fmaf(-INNER_LR * dpred, h2, w3i);
            b3  = fmaf(-INNER_LR, dpred, b3);
            b2i = fmaf(-INNER_LR, dz2, b2i);

            // row update: W2[i][k] -= lr*dz2_i*h1[k]
            const float amr = -INNER_LR * dz2;
            const u64 amrow = pack2(amr, amr);
            #pragma unroll
            for (int k = 0; k < 8; k++) {
                w2row[4 * k]     = fma2(amrow, hp[4 * k],     w2row[4 * k]);
                w2row[4 * k + 1] = fma2(amrow, hp[4 * k + 1], w2row[4 * k + 1]);
                w2row[4 * k + 2] = fma2(amrow, hp[4 * k + 2], w2row[4 * k + 2]);
                w2row[4 * k + 3] = fma2(amrow, hp[4 * k + 3], w2row[4 * k + 3]);
            }

            // fused column pass: dh1 = dpred * sum_j W2old[j][i]*u[j];
            // W2[j][i] -= lr*(dpred*u[j])*h1_i
            const float amc = -INNER_LR * dpred * h1;
            const u64 amcol = pack2(amc, amc);
            const u64* up = (const u64*)us;
            u64 d0 = 0ull, d1 = 0ull, d2 = 0ull, d3 = 0ull;
            #pragma unroll
            for (int j = 0; j < 8; j++) {
                u64 p0 = up[4 * j],     p1 = up[4 * j + 1];
                u64 p2 = up[4 * j + 2], p3 = up[4 * j + 3];
                d0 = fma2(w2col[4 * j],     p0, d0);
                d1 = fma2(w2col[4 * j + 1], p1, d1);
                d2 = fma2(w2col[4 * j + 2], p2, d2);
                d3 = fma2(w2col[4 * j + 3], p3, d3);
                w2col[4 * j]     = fma2(amcol, p0, w2col[4 * j]);
                w2col[4 * j + 1] = fma2(amcol, p1, w2col[4 * j + 1]);
                w2col[4 * j + 2] = fma2(amcol, p2, w2col[4 * j + 2]);
                w2col[4 * j + 3] = fma2(amcol, p3, w2col[4 * j + 3]);
            }
            float2 e0 = unpack2(d0), e1 = unpack2(d1), e2 = unpack2(d2), e3 = unpack2(d3);
            const float dh1 = dpred * (((e0.x + e0.y) + (e1.x + e1.y)) +
                                       ((e2.x + e2.y) + (e3.x + e3.y)));
            const float sech1 = 4.0f * r1 * (1.0f - r1);      // 1 - h1^2
            const float dz1 = dh1 * sech1;
            sdz1 += dz1;
            z1 = fmaf(-INNER_LR * dz1, nrm, z1);              // exact recurrence
        }

        // materialize W1 once per timestep: W1 -= lr * (sum dz1) * [t, x, 1]
        w1a = fmaf(-INNER_LR * sdz1, t_c,    w1a);
        w1b = fmaf(-INNER_LR * sdz1, x_prev, w1b);
        b1i = fmaf(-INNER_LR, sdz1, b1i);

        x_prev = x_true;
    }

    // ---- last output: explicit final forward with final theta ----
    {
        const float tl = ts[T - 1], tp = ts[T - 2];
        const float tin = tl + (tl - tp);
        const float zf = fmaf(w1a, tin, fmaf(w1b, x_prev, b1i)); // x_prev = xs[T-1]
        const float hf = fmaf(-2.0f, tanh_r(zf), 1.0f);
        h1buf[0][i] = hf;
        __syncthreads();

        const u64* hp = (const u64*)h1buf[0];
        u64 a0 = 0ull, a1 = 0ull, a2 = 0ull, a3 = 0ull;
        #pragma unroll
        for (int k = 0; k < 8; k++) {
            a0 = fma2(w2row[4 * k],     hp[4 * k],     a0);
            a1 = fma2(w2row[4 * k + 1], hp[4 * k + 1], a1);
            a2 = fma2(w2row[4 * k + 2], hp[4 * k + 2], a2);
            a3 = fma2(w2row[4 * k + 3], hp[4 * k + 3], a3);
        }
        float2 s0 = unpack2(a0), s1 = unpack2(a1), s2 = unpack2(a2), s3 = unpack2(a3);
        const float z2 = b2i + (((s0.x + s0.y) + (s1.x + s1.y)) +
                                ((s2.x + s2.y) + (s3.x + s3.y)));
        const float h2 = fmaf(-2.0f, tanh_r(z2), 1.0f);
        pps[i] = w3i * h2;
        __syncthreads();
        if (i == 0) out[(size_t)b * T + T - 1] = sum64(pps) + b3;
    }
}

extern "C" void kernel_launch(void* const* d_in, const int* in_sizes, int n_in,
                              void* d_out, int out_size) {
    const float* ts   = (const float*)d_in[0];
    const float* xs   = (const float*)d_in[1];
    const int*   mask = (const int*)  d_in[2];
    const float* W1   = (const float*)d_in[3];
    const float* b1   = (const float*)d_in[4];
    const float* W2   = (const float*)d_in[5];
    const float* b2   = (const float*)d_in[6];
    const float* W3   = (const float*)d_in[7];
    const float* b3   = (const float*)d_in[8];

    const int T = in_sizes[0];
    const int B = in_sizes[1] / T;

    ttt_kernel<<<B, HDIM>>>(ts, xs, mask, W1, b1, W2, b2, W3, b3,
                            (float*)d_out, T);
}

// round 14
// speedup vs baseline: 1.3069x; 1.0499x over previous
#include <cuda_runtime.h>

#define HDIM 64
#define NUM_GRAD_STEPS 4
#define INNER_LR 0.01f

typedef unsigned long long u64;

// ---- packed fp32x2 helpers (ptxas won't auto-fuse; PTX fma.rn.f32x2) ----
__device__ __forceinline__ u64 pack2(float lo, float hi) {
    u64 r; asm("mov.b64 %0, {%1,%2};" : "=l"(r) : "f"(lo), "f"(hi)); return r;
}
__device__ __forceinline__ float2 unpack2(u64 v) {
    float2 f; asm("mov.b64 {%0,%1}, %2;" : "=f"(f.x), "=f"(f.y) : "l"(v)); return f;
}
__device__ __forceinline__ u64 fma2(u64 a, u64 b, u64 c) {
    u64 d; asm("fma.rn.f32x2 %0, %1, %2, %3;" : "=l"(d) : "l"(a), "l"(b), "l"(c)); return d;
}
// full warp sum (used once, in the tail)
__device__ __forceinline__ float warp_sum(float v) {
    #pragma unroll
    for (int off = 16; off; off >>= 1)
        v += __shfl_xor_sync(0xffffffffu, v, off);
    return v;
}

// fast tanh via MUFU: r = 1/(exp(2x)+1); tanh = 1-2r; 1-tanh^2 = 4r(1-r).
__device__ __forceinline__ float tanh_r(float x) {   // returns r
    const float LOG2E2 = 2.885390081777927f;          // 2*log2(e)
    float e; asm("ex2.approx.f32 %0, %1;" : "=f"(e) : "f"(x * LOG2E2));
    float r; asm("rcp.approx.f32 %0, %1;" : "=f"(r) : "f"(e + 1.0f));
    return r;
}

// One block (64 threads) per batch element. Thread i owns hidden unit i.
// W2 lives ONLY in registers (row i + column i as f32x2 pairs).
// Pred reduction: 2 shfls pre-barrier (short chain), 16-partial smem sum after.
__global__ __launch_bounds__(64, 6) void ttt_kernel(
    const float* __restrict__ ts, const float* __restrict__ xs,
    const int*   __restrict__ mask,
    const float* __restrict__ W1g, const float* __restrict__ b1g,
    const float* __restrict__ W2g, const float* __restrict__ b2g,
    const float* __restrict__ W3g, const float* __restrict__ b3g,
    float* __restrict__ out, int T)
{
    __shared__ __align__(16) float h1buf[2][HDIM];
    __shared__ __align__(16) float us[HDIM];
    __shared__ __align__(16) float redv[16];

    const int b    = blockIdx.x;
    const int i    = threadIdx.x;       // 0..63
    const int lane = i & 31;
    const int warp = i >> 5;

    // ---- load theta0 ----
    u64 w2row[32];   // (W2[i][2m], W2[i][2m+1])
    u64 w2col[32];   // (W2[2m][i], W2[2m+1][i])
    #pragma unroll
    for (int k = 0; k < 16; k++) {
        float4 v = *(const float4*)(W2g + i * HDIM + 4 * k);
        w2row[2 * k]     = pack2(v.x, v.y);
        w2row[2 * k + 1] = pack2(v.z, v.w);
    }
    #pragma unroll
    for (int m = 0; m < 32; m++) {
        float lo = W2g[(2 * m) * HDIM + i];
        float hi = W2g[(2 * m + 1) * HDIM + i];
        w2col[m] = pack2(lo, hi);
    }
    float w1a = W1g[2 * i];
    float w1b = W1g[2 * i + 1];
    float b1i = b1g[i];
    float b2i = b2g[i];
    float w3i = W3g[i];
    float b3  = b3g[0];

    const float* xrow = xs + (size_t)b * T;
    const int*   mrow = mask + (size_t)b * (T - 1);

    const float x0 = xrow[0];
    float x_prev = x0;
    if (i == 0) out[(size_t)b * T] = x0;
    __syncthreads();

    float t_c = ts[1], x_true = xrow[1];
    int   mcur = mrow[0];

    for (int s = 1; s < T; s++) {
        float t_n = 0.f, x_n = 0.f; int m_n = 0;
        if (s + 1 < T) { t_n = ts[s + 1]; x_n = xrow[s + 1]; m_n = mrow[s]; }

        float x_t = 0.f;   // fixed at g0

        // z1 recurrence (exact): z1^{g+1} = z1^g - lr*dz1^g*(t^2+x^2+1)
        float z1 = fmaf(w1a, t_c, fmaf(w1b, x_prev, b1i));
        const float nrm = fmaf(t_c, t_c, fmaf(x_prev, x_prev, 1.0f));
        float sdz1 = 0.f;

        #pragma unroll
        for (int g = 0; g < NUM_GRAD_STEPS; g++) {
            float* h1b = h1buf[g & 1];
            // ---- forward at (t_c, x_prev) ----
            const float r1 = tanh_r(z1);
            const float h1 = fmaf(-2.0f, r1, 1.0f);
            h1b[i] = h1;
            __syncthreads();                                  // bar 1

            // matvec: LDS.64 keeps load->fma2 links tight
            const u64* hp = (const u64*)h1b;
            u64 a0 = 0ull, a1 = 0ull, a2 = 0ull, a3 = 0ull;
            #pragma unroll
            for (int k = 0; k < 8; k++) {
                a0 = fma2(w2row[4 * k],     hp[4 * k],     a0);
                a1 = fma2(w2row[4 * k + 1], hp[4 * k + 1], a1);
                a2 = fma2(w2row[4 * k + 2], hp[4 * k + 2], a2);
                a3 = fma2(w2row[4 * k + 3], hp[4 * k + 3], a3);
            }
            float2 s0 = unpack2(a0), s1 = unpack2(a1), s2 = unpack2(a2), s3 = unpack2(a3);
            const float z2 = b2i + (((s0.x + s0.y) + (s1.x + s1.y)) +
                                    ((s2.x + s2.y) + (s3.x + s3.y)));
            const float r2 = tanh_r(z2);
            const float h2 = fmaf(-2.0f, r2, 1.0f);
            const float sech2 = 4.0f * r2 * (1.0f - r2);      // 1 - h2^2

            // u-broadcast + SHORT pre-barrier reduce (2 shfls -> 8 partials/warp)
            const float u = w3i * sech2;
            us[i] = u;
            float v = w3i * h2;
            v += __shfl_xor_sync(0xffffffffu, v, 16);
            v += __shfl_xor_sync(0xffffffffu, v, 8);
            if (lane < 8) redv[warp * 8 + lane] = v;          // lanes 0-7 distinct
            __syncthreads();                                  // bar 2

            // post-barrier: sum 16 partials (4x LDS.128 + tree adds)
            float4 A = *(const float4*)redv;
            float4 Bv = *(const float4*)(redv + 4);
            float4 C = *(const float4*)(redv + 8);
            float4 D = *(const float4*)(redv + 12);
            const float pred = b3 +
                ((((A.x + A.y) + (A.z + A.w)) + ((Bv.x + Bv.y) + (Bv.z + Bv.w))) +
                 (((C.x + C.y) + (C.z + C.w)) + ((D.x + D.y) + (D.z + D.w))));
            if (g == 0) {   // constant-folded under full unroll
                // pred == x_hat_{s-1} (fusion). Emit it and do TF selection.
                const float xh = (s == 1) ? x0 : pred;
                if (s >= 2 && i == 0) out[(size_t)b * T + s - 1] = pred;
                x_t = (mcur != 0) ? x_true : xh;
            }
            const float dpred = 2.0f * (pred - x_t);
            const float dz2   = dpred * u;                    // own dz2 (old W3)

            w3i = fmaf(-INNER_LR * dpred, h2, w3i);
            b3  = fmaf(-INNER_LR, dpred, b3);
            b2i = fmaf(-INNER_LR, dz2, b2i);

            // row update: W2[i][k] -= lr*dz2_i*h1[k]   (LDS.128 + pack)
            const float amr = -INNER_LR * dz2;
            const u64 amrow = pack2(amr, amr);
            const float4* h4 = (const float4*)h1b;
            #pragma unroll
            for (int k = 0; k < 8; k++) {
                float4 Ah = h4[2 * k], Bh = h4[2 * k + 1];
                w2row[4 * k]     = fma2(amrow, pack2(Ah.x, Ah.y), w2row[4 * k]);
                w2row[4 * k + 1] = fma2(amrow, pack2(Ah.z, Ah.w), w2row[4 * k + 1]);
                w2row[4 * k + 2] = fma2(amrow, pack2(Bh.x, Bh.y), w2row[4 * k + 2]);
                w2row[4 * k + 3] = fma2(amrow, pack2(Bh.z, Bh.w), w2row[4 * k + 3]);
            }

            // fused column pass: dh1 = dpred * sum_j W2old[j][i]*u[j];
            // W2[j][i] -= lr*(dpred*u[j])*h1_i          (LDS.128 + pack)
            const float amc = -INNER_LR * dpred * h1;
            const u64 amcol = pack2(amc, amc);
            const float4* u4 = (const float4*)us;
            u64 d0 = 0ull, d1 = 0ull, d2 = 0ull, d3 = 0ull;
            #pragma unroll
            for (int j = 0; j < 8; j++) {
                float4 Au = u4[2 * j], Bu = u4[2 * j + 1];
                u64 p0 = pack2(Au.x, Au.y), p1 = pack2(Au.z, Au.w);
                u64 p2 = pack2(Bu.x, Bu.y), p3 = pack2(Bu.z, Bu.w);
                d0 = fma2(w2col[4 * j],     p0, d0);
                d1 = fma2(w2col[4 * j + 1], p1, d1);
                d2 = fma2(w2col[4 * j + 2], p2, d2);
                d3 = fma2(w2col[4 * j + 3], p3, d3);
                w2col[4 * j]     = fma2(amcol, p0, w2col[4 * j]);
                w2col[4 * j + 1] = fma2(amcol, p1, w2col[4 * j + 1]);
                w2col[4 * j + 2] = fma2(amcol, p2, w2col[4 * j + 2]);
                w2col[4 * j + 3] = fma2(amcol, p3, w2col[4 * j + 3]);
            }
            float2 e0 = unpack2(d0), e1 = unpack2(d1), e2 = unpack2(d2), e3 = unpack2(d3);
            const float dh1 = dpred * (((e0.x + e0.y) + (e1.x + e1.y)) +
                                       ((e2.x + e2.y) + (e3.x + e3.y)));
            const float sech1 = 4.0f * r1 * (1.0f - r1);      // 1 - h1^2
            const float dz1 = dh1 * sech1;
            sdz1 += dz1;
            z1 = fmaf(-INNER_LR * dz1, nrm, z1);              // exact recurrence
        }

        // materialize W1 once per timestep: W1 -= lr * (sum dz1) * [t, x, 1]
        w1a = fmaf(-INNER_LR * sdz1, t_c,    w1a);
        w1b = fmaf(-INNER_LR * sdz1, x_prev, w1b);
        b1i = fmaf(-INNER_LR, sdz1, b1i);

        x_prev = x_true;
        t_c = t_n; x_true = x_n; mcur = m_n;
    }

    // ---- last output: explicit final forward with final theta ----
    {
        const float tl = ts[T - 1], tp = ts[T - 2];
        const float tin = tl + (tl - tp);
        const float zf = fmaf(w1a, tin, fmaf(w1b, x_prev, b1i)); // x_prev = xs[T-1]
        const float hf = fmaf(-2.0f, tanh_r(zf), 1.0f);
        h1buf[0][i] = hf;
        __syncthreads();

        const u64* hp = (const u64*)h1buf[0];
        u64 a0 = 0ull, a1 = 0ull, a2 = 0ull, a3 = 0ull;
        #pragma unroll
        for (int k = 0; k < 8; k++) {
            a0 = fma2(w2row[4 * k],     hp[4 * k],     a0);
            a1 = fma2(w2row[4 * k + 1], hp[4 * k + 1], a1);
            a2 = fma2(w2row[4 * k + 2], hp[4 * k + 2], a2);
            a3 = fma2(w2row[4 * k + 3], hp[4 * k + 3], a3);
        }
        float2 s0 = unpack2(a0), s1 = unpack2(a1), s2 = unpack2(a2), s3 = unpack2(a3);
        const float z2 = b2i + (((s0.x + s0.y) + (s1.x + s1.y)) +
                                ((s2.x + s2.y) + (s3.x + s3.y)));
        const float h2 = fmaf(-2.0f, tanh_r(z2), 1.0f);
        const float pw = warp_sum(w3i * h2);
        if (lane == 0) redv[warp] = pw;
        __syncthreads();
        if (i == 0) out[(size_t)b * T + T - 1] = (redv[0] + redv[1]) + b3;
    }
}

extern "C" void kernel_launch(void* const* d_in, const int* in_sizes, int n_in,
                              void* d_out, int out_size) {
    const float* ts   = (const float*)d_in[0];
    const float* xs   = (const float*)d_in[1];
    const int*   mask = (const int*)  d_in[2];
    const float* W1   = (const float*)d_in[3];
    const float* b1   = (const float*)d_in[4];
    const float* W2   = (const float*)d_in[5];
    const float* b2   = (const float*)d_in[6];
    const float* W3   = (const float*)d_in[7];
    const float* b3   = (const float*)d_in[8];

    const int T = in_sizes[0];
    const int B = in_sizes[1] / T;

    ttt_kernel<<<B, HDIM>>>(ts, xs, mask, W1, b1, W2, b2, W3, b3,
                            (float*)d_out, T);
}

// round 15
// speedup vs baseline: 1.3076x; 1.0005x over previous
#include <cuda_runtime.h>

#define HDIM 64
#define NUM_GRAD_STEPS 4
#define INNER_LR 0.01f

typedef unsigned long long u64;

// ---- packed fp32x2 helpers (ptxas won't auto-fuse; PTX fma.rn.f32x2) ----
__device__ __forceinline__ u64 pack2(float lo, float hi) {
    u64 r; asm("mov.b64 %0, {%1,%2};" : "=l"(r) : "f"(lo), "f"(hi)); return r;
}
__device__ __forceinline__ float2 unpack2(u64 v) {
    float2 f; asm("mov.b64 {%0,%1}, %2;" : "=f"(f.x), "=f"(f.y) : "l"(v)); return f;
}
__device__ __forceinline__ u64 fma2(u64 a, u64 b, u64 c) {
    u64 d; asm("fma.rn.f32x2 %0, %1, %2, %3;" : "=l"(d) : "l"(a), "l"(b), "l"(c)); return d;
}
// full warp sum (used once, in the tail)
__device__ __forceinline__ float warp_sum(float v) {
    #pragma unroll
    for (int off = 16; off; off >>= 1)
        v += __shfl_xor_sync(0xffffffffu, v, off);
    return v;
}

// fast tanh via MUFU: r = 1/(exp(2x)+1); tanh = 1-2r; 1-tanh^2 = 4r(1-r).
__device__ __forceinline__ float tanh_r(float x) {   // returns r
    const float LOG2E2 = 2.885390081777927f;          // 2*log2(e)
    float e; asm("ex2.approx.f32 %0, %1;" : "=f"(e) : "f"(x * LOG2E2));
    float r; asm("rcp.approx.f32 %0, %1;" : "=f"(r) : "f"(e + 1.0f));
    return r;
}

// One block (64 threads) per batch element. Thread i owns hidden unit i.
// W2 lives ONLY in registers (row i + column i as f32x2 pairs).
// Pred reduction: 2 shfls pre-barrier (short chain), 16-partial smem sum after.
__global__ __launch_bounds__(64, 6) void ttt_kernel(
    const float* __restrict__ ts, const float* __restrict__ xs,
    const int*   __restrict__ mask,
    const float* __restrict__ W1g, const float* __restrict__ b1g,
    const float* __restrict__ W2g, const float* __restrict__ b2g,
    const float* __restrict__ W3g, const float* __restrict__ b3g,
    float* __restrict__ out, int T)
{
    __shared__ __align__(16) float h1buf[2][HDIM];
    __shared__ __align__(16) float us[HDIM];
    __shared__ __align__(16) float redv[16];

    const int b    = blockIdx.x;
    const int i    = threadIdx.x;       // 0..63
    const int lane = i & 31;
    const int warp = i >> 5;

    // ---- load theta0 ----
    u64 w2row[32];   // (W2[i][2m], W2[i][2m+1])
    u64 w2col[32];   // (W2[2m][i], W2[2m+1][i])
    #pragma unroll
    for (int k = 0; k < 16; k++) {
        float4 v = *(const float4*)(W2g + i * HDIM + 4 * k);
        w2row[2 * k]     = pack2(v.x, v.y);
        w2row[2 * k + 1] = pack2(v.z, v.w);
    }
    #pragma unroll
    for (int m = 0; m < 32; m++) {
        float lo = W2g[(2 * m) * HDIM + i];
        float hi = W2g[(2 * m + 1) * HDIM + i];
        w2col[m] = pack2(lo, hi);
    }
    float w1a = W1g[2 * i];
    float w1b = W1g[2 * i + 1];
    float b1i = b1g[i];
    float b2i = b2g[i];
    float w3i = W3g[i];
    float b3  = b3g[0];

    const float* xrow = xs + (size_t)b * T;
    const int*   mrow = mask + (size_t)b * (T - 1);

    const float x0 = xrow[0];
    float x_prev = x0;
    if (i == 0) out[(size_t)b * T] = x0;
    __syncthreads();

    float t_c = ts[1], x_true = xrow[1];
    int   mcur = mrow[0];

    for (int s = 1; s < T; s++) {
        float t_n = 0.f, x_n = 0.f; int m_n = 0;
        if (s + 1 < T) { t_n = ts[s + 1]; x_n = xrow[s + 1]; m_n = mrow[s]; }

        float x_t = 0.f;   // fixed at g0

        // z1 recurrence (exact): z1^{g+1} = z1^g - lr*dz1^g*(t^2+x^2+1)
        float z1 = fmaf(w1a, t_c, fmaf(w1b, x_prev, b1i));
        const float nrm = fmaf(t_c, t_c, fmaf(x_prev, x_prev, 1.0f));
        float sdz1 = 0.f;

        #pragma unroll
        for (int g = 0; g < NUM_GRAD_STEPS; g++) {
            float* h1b = h1buf[g & 1];
            // ---- forward at (t_c, x_prev) ----
            const float r1 = tanh_r(z1);
            const float h1 = fmaf(-2.0f, r1, 1.0f);
            h1b[i] = h1;
            __syncthreads();                                  // bar 1

            // matvec: LDS.64 keeps load->fma2 links tight
            const u64* hp = (const u64*)h1b;
            u64 a0 = 0ull, a1 = 0ull, a2 = 0ull, a3 = 0ull;
            #pragma unroll
            for (int k = 0; k < 8; k++) {
                a0 = fma2(w2row[4 * k],     hp[4 * k],     a0);
                a1 = fma2(w2row[4 * k + 1], hp[4 * k + 1], a1);
                a2 = fma2(w2row[4 * k + 2], hp[4 * k + 2], a2);
                a3 = fma2(w2row[4 * k + 3], hp[4 * k + 3], a3);
            }
            float2 s0 = unpack2(a0), s1 = unpack2(a1), s2 = unpack2(a2), s3 = unpack2(a3);
            const float z2 = b2i + (((s0.x + s0.y) + (s1.x + s1.y)) +
                                    ((s2.x + s2.y) + (s3.x + s3.y)));
            const float r2 = tanh_r(z2);
            const float h2 = fmaf(-2.0f, r2, 1.0f);
            const float sech2 = 4.0f * r2 * (1.0f - r2);      // 1 - h2^2

            // u-broadcast + SHORT pre-barrier reduce (2 shfls -> 8 partials/warp)
            const float u = w3i * sech2;
            us[i] = u;
            float v = w3i * h2;
            v += __shfl_xor_sync(0xffffffffu, v, 16);
            v += __shfl_xor_sync(0xffffffffu, v, 8);
            if (lane < 8) redv[warp * 8 + lane] = v;          // lanes 0-7 distinct
            __syncthreads();                                  // bar 2

            // post-barrier: sum 16 partials (4x LDS.128 + tree adds)
            float4 A = *(const float4*)redv;
            float4 Bv = *(const float4*)(redv + 4);
            float4 C = *(const float4*)(redv + 8);
            float4 D = *(const float4*)(redv + 12);
            const float pred = b3 +
                ((((A.x + A.y) + (A.z + A.w)) + ((Bv.x + Bv.y) + (Bv.z + Bv.w))) +
                 (((C.x + C.y) + (C.z + C.w)) + ((D.x + D.y) + (D.z + D.w))));
            if (g == 0) {   // constant-folded under full unroll
                // pred == x_hat_{s-1} (fusion). Emit it and do TF selection.
                const float xh = (s == 1) ? x0 : pred;
                if (s >= 2 && i == 0) out[(size_t)b * T + s - 1] = pred;
                x_t = (mcur != 0) ? x_true : xh;
            }
            const float dpred = 2.0f * (pred - x_t);
            const float dz2   = dpred * u;                    // own dz2 (old W3)

            w3i = fmaf(-INNER_LR * dpred, h2, w3i);
            b3  = fmaf(-INNER_LR, dpred, b3);
            b2i = fmaf(-INNER_LR, dz2, b2i);

            // row update: W2[i][k] -= lr*dz2_i*h1[k]   (LDS.128 + pack)
            const float amr = -INNER_LR * dz2;
            const u64 amrow = pack2(amr, amr);
            const float4* h4 = (const float4*)h1b;
            #pragma unroll
            for (int k = 0; k < 8; k++) {
                float4 Ah = h4[2 * k], Bh = h4[2 * k + 1];
                w2row[4 * k]     = fma2(amrow, pack2(Ah.x, Ah.y), w2row[4 * k]);
                w2row[4 * k + 1] = fma2(amrow, pack2(Ah.z, Ah.w), w2row[4 * k + 1]);
                w2row[4 * k + 2] = fma2(amrow, pack2(Bh.x, Bh.y), w2row[4 * k + 2]);
                w2row[4 * k + 3] = fma2(amrow, pack2(Bh.z, Bh.w), w2row[4 * k + 3]);
            }

            // fused column pass: dh1 = dpred * sum_j W2old[j][i]*u[j];
            // W2[j][i] -= lr*(dpred*u[j])*h1_i          (LDS.128 + pack)
            const float amc = -INNER_LR * dpred * h1;
            const u64 amcol = pack2(amc, amc);
            const float4* u4 = (const float4*)us;
            u64 d0 = 0ull, d1 = 0ull, d2 = 0ull, d3 = 0ull;
            #pragma unroll
            for (int j = 0; j < 8; j++) {
                float4 Au = u4[2 * j], Bu = u4[2 * j + 1];
                u64 p0 = pack2(Au.x, Au.y), p1 = pack2(Au.z, Au.w);
                u64 p2 = pack2(Bu.x, Bu.y), p3 = pack2(Bu.z, Bu.w);
                d0 = fma2(w2col[4 * j],     p0, d0);
                d1 = fma2(w2col[4 * j + 1], p1, d1);
                d2 = fma2(w2col[4 * j + 2], p2, d2);
                d3 = fma2(w2col[4 * j + 3], p3, d3);
                w2col[4 * j]     = fma2(amcol, p0, w2col[4 * j]);
                w2col[4 * j + 1] = fma2(amcol, p1, w2col[4 * j + 1]);
                w2col[4 * j + 2] = fma2(amcol, p2, w2col[4 * j + 2]);
                w2col[4 * j + 3] = fma2(amcol, p3, w2col[4 * j + 3]);
            }
            float2 e0 = unpack2(d0), e1 = unpack2(d1), e2 = unpack2(d2), e3 = unpack2(d3);
            const float dh1 = dpred * (((e0.x + e0.y) + (e1.x + e1.y)) +
                                       ((e2.x + e2.y) + (e3.x + e3.y)));
            const float sech1 = 4.0f * r1 * (1.0f - r1);      // 1 - h1^2
            const float dz1 = dh1 * sech1;
            sdz1 += dz1;
            z1 = fmaf(-INNER_LR * dz1, nrm, z1);              // exact recurrence
        }

        // materialize W1 once per timestep: W1 -= lr * (sum dz1) * [t, x, 1]
        w1a = fmaf(-INNER_LR * sdz1, t_c,    w1a);
        w1b = fmaf(-INNER_LR * sdz1, x_prev, w1b);
        b1i = fmaf(-INNER_LR, sdz1, b1i);

        x_prev = x_true;
        t_c = t_n; x_true = x_n; mcur = m_n;
    }

    // ---- last output: explicit final forward with final theta ----
    {
        const float tl = ts[T - 1], tp = ts[T - 2];
        const float tin = tl + (tl - tp);
        const float zf = fmaf(w1a, tin, fmaf(w1b, x_prev, b1i)); // x_prev = xs[T-1]
        const float hf = fmaf(-2.0f, tanh_r(zf), 1.0f);
        h1buf[0][i] = hf;
        __syncthreads();

        const u64* hp = (const u64*)h1buf[0];
        u64 a0 = 0ull, a1 = 0ull, a2 = 0ull, a3 = 0ull;
        #pragma unroll
        for (int k = 0; k < 8; k++) {
            a0 = fma2(w2row[4 * k],     hp[4 * k],     a0);
            a1 = fma2(w2row[4 * k + 1], hp[4 * k + 1], a1);
            a2 = fma2(w2row[4 * k + 2], hp[4 * k + 2], a2);
            a3 = fma2(w2row[4 * k + 3], hp[4 * k + 3], a3);
        }
        float2 s0 = unpack2(a0), s1 = unpack2(a1), s2 = unpack2(a2), s3 = unpack2(a3);
        const float z2 = b2i + (((s0.x + s0.y) + (s1.x + s1.y)) +
                                ((s2.x + s2.y) + (s3.x + s3.y)));
        const float h2 = fmaf(-2.0f, tanh_r(z2), 1.0f);
        const float pw = warp_sum(w3i * h2);
        if (lane == 0) redv[warp] = pw;
        __syncthreads();
        if (i == 0) out[(size_t)b * T + T - 1] = (redv[0] + redv[1]) + b3;
    }
}

extern "C" void kernel_launch(void* const* d_in, const int* in_sizes, int n_in,
                              void* d_out, int out_size) {
    const float* ts   = (const float*)d_in[0];
    const float* xs   = (const float*)d_in[1];
    const int*   mask = (const int*)  d_in[2];
    const float* W1   = (const float*)d_in[3];
    const float* b1   = (const float*)d_in[4];
    const float* W2   = (const float*)d_in[5];
    const float* b2   = (const float*)d_in[6];
    const float* W3   = (const float*)d_in[7];
    const float* b3   = (const float*)d_in[8];

    const int T = in_sizes[0];
    const int B = in_sizes[1] / T;

    ttt_kernel<<<B, HDIM>>>(ts, xs, mask, W1, b1, W2, b2, W3, b3,
                            (float*)d_out, T);
}

// round 16
// speedup vs baseline: 1.3086x; 1.0008x over previous
#include <cuda_runtime.h>

#define HDIM 64
#define NUM_GRAD_STEPS 4
#define INNER_LR 0.01f

typedef unsigned long long u64;

// ---- packed fp32x2 helpers (ptxas won't auto-fuse; PTX fma.rn.f32x2) ----
__device__ __forceinline__ u64 pack2(float lo, float hi) {
    u64 r; asm("mov.b64 %0, {%1,%2};" : "=l"(r) : "f"(lo), "f"(hi)); return r;
}
__device__ __forceinline__ float2 unpack2(u64 v) {
    float2 f; asm("mov.b64 {%0,%1}, %2;" : "=f"(f.x), "=f"(f.y) : "l"(v)); return f;
}
__device__ __forceinline__ u64 fma2(u64 a, u64 b, u64 c) {
    u64 d; asm("fma.rn.f32x2 %0, %1, %2, %3;" : "=l"(d) : "l"(a), "l"(b), "l"(c)); return d;
}
// full warp sum (used once, in the tail)
__device__ __forceinline__ float warp_sum(float v) {
    #pragma unroll
    for (int off = 16; off; off >>= 1)
        v += __shfl_xor_sync(0xffffffffu, v, off);
    return v;
}

// fast tanh via MUFU: r = 1/(exp(2x)+1); tanh = 1-2r; 1-tanh^2 = 4r(1-r).
__device__ __forceinline__ float tanh_r(float x) {   // returns r
    const float LOG2E2 = 2.885390081777927f;          // 2*log2(e)
    float e; asm("ex2.approx.f32 %0, %1;" : "=f"(e) : "f"(x * LOG2E2));
    float r; asm("rcp.approx.f32 %0, %1;" : "=f"(r) : "f"(e + 1.0f));
    return r;
}

// One block (64 threads) per batch element. Thread i owns hidden unit i.
// W2 lives ONLY in registers (row i + column i as f32x2 pairs).
// Pred reduction: 2 shfls pre-barrier (short chain), 16-partial smem sum after.
__global__ __launch_bounds__(64, 6) void ttt_kernel(
    const float* __restrict__ ts, const float* __restrict__ xs,
    const int*   __restrict__ mask,
    const float* __restrict__ W1g, const float* __restrict__ b1g,
    const float* __restrict__ W2g, const float* __restrict__ b2g,
    const float* __restrict__ W3g, const float* __restrict__ b3g,
    float* __restrict__ out, int T)
{
    __shared__ __align__(16) float h1buf[2][HDIM];
    __shared__ __align__(16) float us[HDIM];
    __shared__ __align__(16) float redv[16];

    const int b    = blockIdx.x;
    const int i    = threadIdx.x;       // 0..63
    const int lane = i & 31;
    const int warp = i >> 5;

    // ---- load theta0 ----
    u64 w2row[32];   // (W2[i][2m], W2[i][2m+1])
    u64 w2col[32];   // (W2[2m][i], W2[2m+1][i])
    #pragma unroll
    for (int k = 0; k < 16; k++) {
        float4 v = *(const float4*)(W2g + i * HDIM + 4 * k);
        w2row[2 * k]     = pack2(v.x, v.y);
        w2row[2 * k + 1] = pack2(v.z, v.w);
    }
    #pragma unroll
    for (int m = 0; m < 32; m++) {
        float lo = W2g[(2 * m) * HDIM + i];
        float hi = W2g[(2 * m + 1) * HDIM + i];
        w2col[m] = pack2(lo, hi);
    }
    float w1a = W1g[2 * i];
    float w1b = W1g[2 * i + 1];
    float b1i = b1g[i];
    float b2i = b2g[i];
    float w3i = W3g[i];
    float b3  = b3g[0];

    const float* xrow = xs + (size_t)b * T;
    const int*   mrow = mask + (size_t)b * (T - 1);

    const float x0 = xrow[0];
    float x_prev = x0;
    if (i == 0) out[(size_t)b * T] = x0;
    __syncthreads();

    float t_c = ts[1], x_true = xrow[1];
    int   mcur = mrow[0];

    for (int s = 1; s < T; s++) {
        float t_n = 0.f, x_n = 0.f; int m_n = 0;
        if (s + 1 < T) { t_n = ts[s + 1]; x_n = xrow[s + 1]; m_n = mrow[s]; }

        float x_t = 0.f;   // fixed at g0

        // z1 recurrence (exact): z1^{g+1} = z1^g - lr*dz1^g*(t^2+x^2+1)
        float z1 = fmaf(w1a, t_c, fmaf(w1b, x_prev, b1i));
        const float nrm = fmaf(t_c, t_c, fmaf(x_prev, x_prev, 1.0f));
        float sdz1 = 0.f;

        #pragma unroll
        for (int g = 0; g < NUM_GRAD_STEPS; g++) {
            float* h1b = h1buf[g & 1];
            // ---- forward at (t_c, x_prev) ----
            const float r1 = tanh_r(z1);
            const float h1 = fmaf(-2.0f, r1, 1.0f);
            h1b[i] = h1;
            __syncthreads();                                  // bar 1

            // matvec: LDS.64 keeps load->fma2 links tight
            const u64* hp = (const u64*)h1b;
            u64 a0 = 0ull, a1 = 0ull, a2 = 0ull, a3 = 0ull;
            #pragma unroll
            for (int k = 0; k < 8; k++) {
                a0 = fma2(w2row[4 * k],     hp[4 * k],     a0);
                a1 = fma2(w2row[4 * k + 1], hp[4 * k + 1], a1);
                a2 = fma2(w2row[4 * k + 2], hp[4 * k + 2], a2);
                a3 = fma2(w2row[4 * k + 3], hp[4 * k + 3], a3);
            }
            float2 s0 = unpack2(a0), s1 = unpack2(a1), s2 = unpack2(a2), s3 = unpack2(a3);
            const float z2 = b2i + (((s0.x + s0.y) + (s1.x + s1.y)) +
                                    ((s2.x + s2.y) + (s3.x + s3.y)));
            const float r2 = tanh_r(z2);
            const float h2 = fmaf(-2.0f, r2, 1.0f);
            const float sech2 = 4.0f * r2 * (1.0f - r2);      // 1 - h2^2

            // u-broadcast + SHORT pre-barrier reduce (2 shfls -> 8 partials/warp)
            const float u = w3i * sech2;
            us[i] = u;
            float v = w3i * h2;
            v += __shfl_xor_sync(0xffffffffu, v, 16);
            v += __shfl_xor_sync(0xffffffffu, v, 8);
            if (lane < 8) redv[warp * 8 + lane] = v;          // lanes 0-7 distinct
            __syncthreads();                                  // bar 2

            // post-barrier: sum 16 partials (4x LDS.128 + tree adds)
            float4 A = *(const float4*)redv;
            float4 Bv = *(const float4*)(redv + 4);
            float4 C = *(const float4*)(redv + 8);
            float4 D = *(const float4*)(redv + 12);
            const float pred = b3 +
                ((((A.x + A.y) + (A.z + A.w)) + ((Bv.x + Bv.y) + (Bv.z + Bv.w))) +
                 (((C.x + C.y) + (C.z + C.w)) + ((D.x + D.y) + (D.z + D.w))));
            if (g == 0) {   // constant-folded under full unroll
                // pred == x_hat_{s-1} (fusion). Emit it and do TF selection.
                const float xh = (s == 1) ? x0 : pred;
                if (s >= 2 && i == 0) out[(size_t)b * T + s - 1] = pred;
                x_t = (mcur != 0) ? x_true : xh;
            }
            const float dpred = 2.0f * (pred - x_t);
            const float dz2   = dpred * u;                    // own dz2 (old W3)

            w3i = fmaf(-INNER_LR * dpred, h2, w3i);
            b3  = fmaf(-INNER_LR, dpred, b3);
            b2i = fmaf(-INNER_LR, dz2, b2i);

            // row update: W2[i][k] -= lr*dz2_i*h1[k]   (LDS.128 + pack)
            const float amr = -INNER_LR * dz2;
            const u64 amrow = pack2(amr, amr);
            const float4* h4 = (const float4*)h1b;
            #pragma unroll
            for (int k = 0; k < 8; k++) {
                float4 Ah = h4[2 * k], Bh = h4[2 * k + 1];
                w2row[4 * k]     = fma2(amrow, pack2(Ah.x, Ah.y), w2row[4 * k]);
                w2row[4 * k + 1] = fma2(amrow, pack2(Ah.z, Ah.w), w2row[4 * k + 1]);
                w2row[4 * k + 2] = fma2(amrow, pack2(Bh.x, Bh.y), w2row[4 * k + 2]);
                w2row[4 * k + 3] = fma2(amrow, pack2(Bh.z, Bh.w), w2row[4 * k + 3]);
            }

            // fused column pass: dh1 = dpred * sum_j W2old[j][i]*u[j];
            // W2[j][i] -= lr*(dpred*u[j])*h1_i          (LDS.128 + pack)
            const float amc = -INNER_LR * dpred * h1;
            const u64 amcol = pack2(amc, amc);
            const float4* u4 = (const float4*)us;
            u64 d0 = 0ull, d1 = 0ull, d2 = 0ull, d3 = 0ull;
            #pragma unroll
            for (int j = 0; j < 8; j++) {
                float4 Au = u4[2 * j], Bu = u4[2 * j + 1];
                u64 p0 = pack2(Au.x, Au.y), p1 = pack2(Au.z, Au.w);
                u64 p2 = pack2(Bu.x, Bu.y), p3 = pack2(Bu.z, Bu.w);
                d0 = fma2(w2col[4 * j],     p0, d0);
                d1 = fma2(w2col[4 * j + 1], p1, d1);
                d2 = fma2(w2col[4 * j + 2], p2, d2);
                d3 = fma2(w2col[4 * j + 3], p3, d3);
                w2col[4 * j]     = fma2(amcol, p0, w2col[4 * j]);
                w2col[4 * j + 1] = fma2(amcol, p1, w2col[4 * j + 1]);
                w2col[4 * j + 2] = fma2(amcol, p2, w2col[4 * j + 2]);
                w2col[4 * j + 3] = fma2(amcol, p3, w2col[4 * j + 3]);
            }
            float2 e0 = unpack2(d0), e1 = unpack2(d1), e2 = unpack2(d2), e3 = unpack2(d3);
            const float dh1 = dpred * (((e0.x + e0.y) + (e1.x + e1.y)) +
                                       ((e2.x + e2.y) + (e3.x + e3.y)));
            const float sech1 = 4.0f * r1 * (1.0f - r1);      // 1 - h1^2
            const float dz1 = dh1 * sech1;
            sdz1 += dz1;
            z1 = fmaf(-INNER_LR * dz1, nrm, z1);              // exact recurrence
        }

        // materialize W1 once per timestep: W1 -= lr * (sum dz1) * [t, x, 1]
        w1a = fmaf(-INNER_LR * sdz1, t_c,    w1a);
        w1b = fmaf(-INNER_LR * sdz1, x_prev, w1b);
        b1i = fmaf(-INNER_LR, sdz1, b1i);

        x_prev = x_true;
        t_c = t_n; x_true = x_n; mcur = m_n;
    }

    // ---- last output: explicit final forward with final theta ----
    {
        const float tl = ts[T - 1], tp = ts[T - 2];
        const float tin = tl + (tl - tp);
        const float zf = fmaf(w1a, tin, fmaf(w1b, x_prev, b1i)); // x_prev = xs[T-1]
        const float hf = fmaf(-2.0f, tanh_r(zf), 1.0f);
        h1buf[0][i] = hf;
        __syncthreads();

        const u64* hp = (const u64*)h1buf[0];
        u64 a0 = 0ull, a1 = 0ull, a2 = 0ull, a3 = 0ull;
        #pragma unroll
        for (int k = 0; k < 8; k++) {
            a0 = fma2(w2row[4 * k],     hp[4 * k],     a0);
            a1 = fma2(w2row[4 * k + 1], hp[4 * k + 1], a1);
            a2 = fma2(w2row[4 * k + 2], hp[4 * k + 2], a2);
            a3 = fma2(w2row[4 * k + 3], hp[4 * k + 3], a3);
        }
        float2 s0 = unpack2(a0), s1 = unpack2(a1), s2 = unpack2(a2), s3 = unpack2(a3);
        const float z2 = b2i + (((s0.x + s0.y) + (s1.x + s1.y)) +
                                ((s2.x + s2.y) + (s3.x + s3.y)));
        const float h2 = fmaf(-2.0f, tanh_r(z2), 1.0f);
        const float pw = warp_sum(w3i * h2);
        if (lane == 0) redv[warp] = pw;
        __syncthreads();
        if (i == 0) out[(size_t)b * T + T - 1] = (redv[0] + redv[1]) + b3;
    }
}

extern "C" void kernel_launch(void* const* d_in, const int* in_sizes, int n_in,
                              void* d_out, int out_size) {
    const float* ts   = (const float*)d_in[0];
    const float* xs   = (const float*)d_in[1];
    const int*   mask = (const int*)  d_in[2];
    const float* W1   = (const float*)d_in[3];
    const float* b1   = (const float*)d_in[4];
    const float* W2   = (const float*)d_in[5];
    const float* b2   = (const float*)d_in[6];
    const float* W3   = (const float*)d_in[7];
    const float* b3   = (const float*)d_in[8];

    const int T = in_sizes[0];
    const int B = in_sizes[1] / T;

    ttt_kernel<<<B, HDIM>>>(ts, xs, mask, W1, b1, W2, b2, W3, b3,
                            (float*)d_out, T);
}